// round 1
// baseline (speedup 1.0000x reference)
#include <cuda_runtime.h>
#include <math.h>

#define T_DIM 512
#define B_DIM 1024
#define K_DIM 48
#define START_TAG 46
#define STOP_TAG 47
#define NEG_VAL -10000.0f

#define WARPS_PER_BLOCK 8
#define THREADS (WARPS_PER_BLOCK * 32)
#define FULLMASK 0xffffffffu

__global__ void crf_zero_out(float* out) { out[0] = 0.0f; }

__global__ __launch_bounds__(THREADS, 2) void crf_forward_kernel(
    const float* __restrict__ feats,      // (T, B, K)
    const float* __restrict__ trans,      // (K, K)  [next, prev]
    const int*   __restrict__ tags,       // (B, T)
    const int*   __restrict__ lengths,    // (B,)
    float* __restrict__ out)              // scalar
{
    __shared__ float trans_sh[K_DIM * K_DIM];
    __shared__ __align__(16) float a_sh[WARPS_PER_BLOCK][K_DIM];

    const int tid = threadIdx.x;
    for (int i = tid; i < K_DIM * K_DIM; i += THREADS) trans_sh[i] = trans[i];
    __syncthreads();

    const int warp = tid >> 5;
    const int lane = tid & 31;
    const int b = blockIdx.x * WARPS_PER_BLOCK + warp;
    const int j0 = lane;
    const int j1 = lane + 32;
    const bool has1 = (lane < 16);

    // E rows in registers: E[j][i] = exp(trans[j][i]); NEG rows/cols underflow to 0.
    float E0[K_DIM], E1[K_DIM];
#pragma unroll
    for (int i = 0; i < K_DIM; i++) {
        E0[i] = __expf(trans_sh[j0 * K_DIM + i]);
        E1[i] = has1 ? __expf(trans_sh[j1 * K_DIM + i]) : 0.0f;
    }

    const int len = lengths[b];                 // len in [1, T]
    const int stride = B_DIM * K_DIM;           // floats per time step
    const float* fb = feats + b * K_DIM;        // feats[(t*B + b)*K + j] = fb[t*stride + j]
    const int* tagb = tags + b * T_DIM;

    // ---- t = 0 (analytic: only START has weight; matches reference within fp32) ----
    float alpha0 = fb[j0] + trans_sh[j0 * K_DIM + START_TAG];
    float alpha1 = has1 ? (fb[j1] + trans_sh[j1 * K_DIM + START_TAG]) : NEG_VAL;

    // gold score, computed uniformly across the warp (broadcast loads)
    int prev = tagb[0];
    float gold = trans_sh[prev * K_DIM + START_TAG] + fb[prev];

    // ---- main recurrence, t = 1 .. len-1, with feat/tag prefetch ----
    float pf0 = 0.0f, pf1 = 0.0f;
    int ptag = 0;
    if (len > 1) {
        const float* ft = fb + stride;
        pf0 = ft[j0];
        pf1 = has1 ? ft[j1] : 0.0f;
        ptag = tagb[1];
    }

    for (int t = 1; t < len; t++) {
        const float feat0 = pf0;
        const float feat1 = pf1;
        const int nexttag = ptag;
        if (t + 1 < len) {
            const float* ft = fb + (t + 1) * stride;
            pf0 = ft[j0];
            pf1 = has1 ? ft[j1] : 0.0f;
            ptag = tagb[t + 1];
        }

        // reference point: alpha[0] (finite for t>=1; spread bounded ~±11 so no overflow)
        const float m = __shfl_sync(FULLMASK, alpha0, 0);
        const float a0 = __expf(alpha0 - m);
        const float a1 = __expf(alpha1 - m);   // lanes>=16: alpha1 = -inf -> 0 (never stored)

        __syncwarp();                          // prior step's readers done before overwrite
        a_sh[warp][lane] = a0;
        if (has1) a_sh[warp][lane + 32] = a1;
        __syncwarp();

        float s0a = 0.f, s0b = 0.f, s1a = 0.f, s1b = 0.f;
        const float4* av = (const float4*)a_sh[warp];
#pragma unroll
        for (int i4 = 0; i4 < K_DIM / 4; i4++) {
            const float4 a = av[i4];
            const int i = i4 * 4;
            s0a = fmaf(a.x, E0[i + 0], s0a);
            s0b = fmaf(a.y, E0[i + 1], s0b);
            s0a = fmaf(a.z, E0[i + 2], s0a);
            s0b = fmaf(a.w, E0[i + 3], s0b);
            s1a = fmaf(a.x, E1[i + 0], s1a);
            s1b = fmaf(a.y, E1[i + 1], s1b);
            s1a = fmaf(a.z, E1[i + 2], s1a);
            s1b = fmaf(a.w, E1[i + 3], s1b);
        }

        alpha0 = feat0 + m + __logf(s0a + s0b);
        alpha1 = feat1 + m + __logf(s1a + s1b);   // lanes>=16: log(0) = -inf, stays dead

        // gold: trans[next, prev] + feats[t, b, next]  (uniform broadcast)
        gold += trans_sh[nexttag * K_DIM + prev] + fb[t * stride + nexttag];
        prev = nexttag;
    }

    // ---- log_z = lse_j(alpha_j + trans[STOP, j]) ----
    float v0 = alpha0 + trans_sh[STOP_TAG * K_DIM + j0];
    float v1 = has1 ? (alpha1 + trans_sh[STOP_TAG * K_DIM + j1]) : -INFINITY;
    float mv = fmaxf(v0, v1);
#pragma unroll
    for (int off = 16; off > 0; off >>= 1)
        mv = fmaxf(mv, __shfl_xor_sync(FULLMASK, mv, off));
    float se = __expf(v0 - mv) + (has1 ? __expf(v1 - mv) : 0.0f);
#pragma unroll
    for (int off = 16; off > 0; off >>= 1)
        se += __shfl_xor_sync(FULLMASK, se, off);
    const float log_z = mv + __logf(se);

    gold += trans_sh[STOP_TAG * K_DIM + prev];   // trans[STOP, last_tag]

    if (lane == 0) atomicAdd(out, log_z - gold);
}

extern "C" void kernel_launch(void* const* d_in, const int* in_sizes, int n_in,
                              void* d_out, int out_size) {
    const float* feats   = (const float*)d_in[0];
    const float* trans   = (const float*)d_in[1];
    const int*   tags    = (const int*)d_in[2];
    const int*   lengths = (const int*)d_in[3];
    float* out = (float*)d_out;

    crf_zero_out<<<1, 1>>>(out);
    crf_forward_kernel<<<B_DIM / WARPS_PER_BLOCK, THREADS>>>(feats, trans, tags, lengths, out);
}